// round 7
// baseline (speedup 1.0000x reference)
#include <cuda_runtime.h>
#include <cstdint>

// QuantumCircuitSimulator2: 24 qubits, 8 steps of 4-qubit (16x16 complex) gates.
// 3-step fusion in a 4096-amplitude SMEM tile (float2, skew a = s + (s>>4)).
// G=2 groups per thread: each gate-table row read (the LSU bottleneck) is
// amortized over two 16-amplitude groups. 128 threads/block, <=170 regs.

#define NQ 24
#define NSTATE (1u << NQ)
#define TILE_BITS 12
#define TILE (1u << TILE_BITS)
#define NBLOCKS (1u << (NQ - TILE_BITS))
#define PLANE (TILE + (TILE >> 4))     // 4352 float2

#define SADDR2(s) ((s) + ((s) >> 4))

typedef unsigned long long u64;

__device__ __forceinline__ u64 fma2(u64 a, u64 b, u64 c) {
    u64 d;
    asm("fma.rn.f32x2 %0, %1, %2, %3;" : "=l"(d) : "l"(a), "l"(b), "l"(c));
    return d;
}
__device__ __forceinline__ u64 add2(u64 a, u64 b) {
    u64 d;
    asm("add.rn.f32x2 %0, %1, %2;" : "=l"(d) : "l"(a), "l"(b));
    return d;
}
__device__ __forceinline__ u64 pack2(float lo, float hi) {
    u64 d;
    asm("mov.b64 %0, {%1, %2};" : "=l"(d) : "f"(lo), "f"(hi));
    return d;
}
__device__ __forceinline__ void unpack2(u64 v, float& lo, float& hi) {
    asm("mov.b64 {%0, %1}, %2;" : "=f"(lo), "=f"(hi) : "l"(v));
}

// One 16x16 complex gate applied to TWO groups (amortizes table reads).
// sG: Karatsuba tables (A=gr, B=gr+gi, C=gi-gr), 256 floats each.
// aB0/aB1: skewed base addresses of the two groups; K0..K3: skew-additive
// address increments of the gate's 4 target slots.
__device__ __forceinline__ void apply_gate2(float2* __restrict__ S,
                                            const float* __restrict__ sG,
                                            unsigned aB0, unsigned aB1,
                                            unsigned K0, unsigned K1,
                                            unsigned K2, unsigned K3) {
    u64 sr2a[8], si2a[8], u2a[8];
    u64 sr2b[8], si2b[8], u2b[8];
#pragma unroll
    for (int kk = 0; kk < 8; kk++) {
        unsigned off = ((kk & 1) ? K1 : 0u) + ((kk & 2) ? K2 : 0u) +
                       ((kk & 4) ? K3 : 0u);
        float2 c0 = S[aB0 + off];
        float2 c1 = S[aB0 + off + K0];
        float2 d0 = S[aB1 + off];
        float2 d1 = S[aB1 + off + K0];
        sr2a[kk] = pack2(c0.x, c1.x);
        si2a[kk] = pack2(c0.y, c1.y);
        u2a[kk]  = add2(sr2a[kk], si2a[kk]);
        sr2b[kk] = pack2(d0.x, d1.x);
        si2b[kk] = pack2(d0.y, d1.y);
        u2b[kk]  = add2(sr2b[kk], si2b[kk]);
    }
    const u64 NEG1 = pack2(-1.0f, -1.0f);
#pragma unroll
    for (int j = 0; j < 16; j++) {
        const float4* A4 = reinterpret_cast<const float4*>(sG + j * 16);
        const float4* B4 = reinterpret_cast<const float4*>(sG + 256 + j * 16);
        const float4* C4 = reinterpret_cast<const float4*>(sG + 512 + j * 16);
        u64 a1a = 0ull, a2a = 0ull, a3a = 0ull;
        u64 a1b = 0ull, a2b = 0ull, a3b = 0ull;
#pragma unroll
        for (int q = 0; q < 4; q++) {
            float4 av = A4[q], bv = B4[q], cv = C4[q];
            u64 aLo = pack2(av.x, av.y), aHi = pack2(av.z, av.w);
            u64 bLo = pack2(bv.x, bv.y), bHi = pack2(bv.z, bv.w);
            u64 cLo = pack2(cv.x, cv.y), cHi = pack2(cv.z, cv.w);
            a1a = fma2(aLo, u2a[2 * q], a1a);
            a2a = fma2(bLo, si2a[2 * q], a2a);
            a3a = fma2(cLo, sr2a[2 * q], a3a);
            a1b = fma2(aLo, u2b[2 * q], a1b);
            a2b = fma2(bLo, si2b[2 * q], a2b);
            a3b = fma2(cLo, sr2b[2 * q], a3b);
            a1a = fma2(aHi, u2a[2 * q + 1], a1a);
            a2a = fma2(bHi, si2a[2 * q + 1], a2a);
            a3a = fma2(cHi, sr2a[2 * q + 1], a3a);
            a1b = fma2(aHi, u2b[2 * q + 1], a1b);
            a2b = fma2(bHi, si2b[2 * q + 1], a2b);
            a3b = fma2(cHi, sr2b[2 * q + 1], a3b);
        }
        unsigned jo = ((j & 1) ? K0 : 0u) + ((j & 2) ? K1 : 0u) +
                      ((j & 4) ? K2 : 0u) + ((j & 8) ? K3 : 0u);
        {
            u64 dre = fma2(a2a, NEG1, a1a);
            u64 dim = add2(a1a, a3a);
            float rl, rh, il, ih;
            unpack2(dre, rl, rh);
            unpack2(dim, il, ih);
            S[aB0 + jo] = make_float2(rl + rh, il + ih);
        }
        {
            u64 dre = fma2(a2b, NEG1, a1b);
            u64 dim = add2(a1b, a3b);
            float rl, rh, il, ih;
            unpack2(dre, rl, rh);
            unpack2(dim, il, ih);
            S[aB1 + jo] = make_float2(rl + rh, il + ih);
        }
    }
}

__global__ __launch_bounds__(128, 3)
void qstep3_kernel(const float* __restrict__ src,
                   float* __restrict__ dst,
                   const float* __restrict__ gates,
                   const int* __restrict__ targets_raw,
                   int stepA, int stepB, int stepC) {
    __shared__ __align__(16) float2 S[PLANE];
    __shared__ __align__(16) float sG[3][768];
    __shared__ int pArr[12];        // physical bits of V (ascending)
    __shared__ int slotArr[12];     // SMEM slot of bit pArr[j]
    __shared__ int bK[2][4];        // skew-additive K of gate B/C target slots
    __shared__ int nbArr[2][8];     // non-target slots (ascending): B, C
    __shared__ unsigned uVmask;

    const int tid = threadIdx.x;
    const int ngates = (stepC >= 0) ? 3 : 2;

    // ---- Karatsuba gate tables ----
    {
        int steps[3] = {stepA, stepB, stepC};
        for (int g = 0; g < ngates; g++) {
            const float* gp = gates + (size_t)steps[g] * 512;
            for (int i = tid; i < 768; i += 128) {
                int t = i >> 8;
                int idx = i & 255;
                float gr = gp[idx], gi = gp[256 + idx];
                sG[g][i] = (t == 0) ? gr : ((t == 1) ? (gr + gi) : (gi - gr));
            }
        }
    }

    // ---- per-block setup ----
    if (tid == 0) {
        int stride = (targets_raw[1] == 0 && targets_raw[3] == 0) ? 2 : 1;
        int steps[3] = {stepA, stepB, stepC};
        int q[3][4];
        for (int g = 0; g < ngates; g++)
            for (int t = 0; t < 4; t++)
                q[g][t] = targets_raw[(steps[g] * 4 + t) * stride];

        unsigned U = 0;
        for (int g = 0; g < ngates; g++)
            for (int t = 0; t < 4; t++) U |= 1u << q[g][t];
        unsigned V = U;
        int need = TILE_BITS - __popc(U);
        for (int b = 0; need > 0; b++)
            if (!((V >> b) & 1u)) { V |= 1u << b; need--; }
        uVmask = V;

        int slot_of[24];
        for (int b = 0; b < 24; b++) slot_of[b] = -1;
        for (int t = 0; t < 4; t++) slot_of[q[0][t]] = 8 + t;  // A: slots 8..11
        int hi = 7;
        for (int g = 1; g < ngates; g++)
            for (int t = 0; t < 4; t++)
                if (slot_of[q[g][t]] < 0) slot_of[q[g][t]] = hi--;
        int fs = 0;
        for (int b = 0; b < 24; b++)
            if (((V >> b) & 1u) && slot_of[b] < 0) slot_of[b] = fs++;

        int j = 0;
        for (int b = 0; b < 24; b++)
            if ((V >> b) & 1u) { pArr[j] = b; slotArr[j] = slot_of[b]; j++; }

        for (int g = 1; g < ngates; g++) {
            unsigned tm = 0;
            for (int t = 0; t < 4; t++) {
                unsigned m = 1u << slot_of[q[g][t]];
                bK[g - 1][t] = (int)(m + (m >> 4));  // skew-additive K
                tm |= m;
            }
            int jj = 0;
            for (int s3 = 0; s3 < 12; s3++)
                if (!((tm >> s3) & 1u)) nbArr[g - 1][jj++] = s3;
        }
    }
    __syncthreads();

    // ---- per-thread mappings ----
    const unsigned V = uVmask;
    unsigned outer = 0;
    {
        unsigned ob = blockIdx.x;
        for (int b = 0; b < 24; b++)
            if (!((V >> b) & 1u)) { outer |= (ob & 1u) << b; ob >>= 1; }
    }
    // Two groups per thread: gid_h = tid + 128*h  (8-bit group ids)
    unsigned gLoH[2], sLoH[2];
#pragma unroll
    for (int h = 0; h < 2; h++) {
        unsigned gid = (unsigned)tid + 128u * h;
        unsigned gLo = 0, sLo = 0;
#pragma unroll
        for (int j = 0; j < 8; j++)
            if ((gid >> j) & 1) { gLo |= 1u << pArr[j]; sLo |= 1u << slotArr[j]; }
        gLoH[h] = gLo;
        sLoH[h] = sLo;
    }

    const float* __restrict__ srcRe = src;
    const float* __restrict__ srcIm = src + NSTATE;

    // ---- copy-in: coalesced global -> permuted SMEM (float2) ----
#pragma unroll
    for (int h = 0; h < 2; h++) {
#pragma unroll
        for (int cc = 0; cc < 16; cc++) {
            unsigned gHi = 0, sHi = 0;
#pragma unroll
            for (int jj = 0; jj < 4; jj++)
                if ((cc >> jj) & 1) {
                    gHi |= 1u << pArr[8 + jj];
                    sHi |= 1u << slotArr[8 + jj];
                }
            unsigned g = outer + gHi + gLoH[h];
            S[SADDR2(sHi + sLoH[h])] = make_float2(srcRe[g], srcIm[g]);
        }
    }
    __syncthreads();

    // ---- gate A: targets at slots 8..11 (gate order), groups = slots 0..7 ----
    // K(m) = m + (m>>4): 256->272, 512->544, 1024->1088, 2048->2176
    apply_gate2(S, sG[0], SADDR2((unsigned)tid), SADDR2((unsigned)tid + 128u),
                272u, 544u, 1088u, 2176u);
    __syncthreads();

    // ---- gate B ----
    {
        unsigned b0 = 0, b1 = 0;
#pragma unroll
        for (int j = 0; j < 8; j++) {
            if ((tid >> j) & 1) b0 |= 1u << nbArr[0][j];
            if ((((unsigned)tid + 128u) >> j) & 1) b1 |= 1u << nbArr[0][j];
        }
        apply_gate2(S, sG[1], SADDR2(b0), SADDR2(b1), (unsigned)bK[0][0],
                    (unsigned)bK[0][1], (unsigned)bK[0][2], (unsigned)bK[0][3]);
    }
    __syncthreads();

    // ---- gate C (optional) ----
    if (ngates == 3) {
        unsigned b0 = 0, b1 = 0;
#pragma unroll
        for (int j = 0; j < 8; j++) {
            if ((tid >> j) & 1) b0 |= 1u << nbArr[1][j];
            if ((((unsigned)tid + 128u) >> j) & 1) b1 |= 1u << nbArr[1][j];
        }
        apply_gate2(S, sG[2], SADDR2(b0), SADDR2(b1), (unsigned)bK[1][0],
                    (unsigned)bK[1][1], (unsigned)bK[1][2], (unsigned)bK[1][3]);
        __syncthreads();
    }

    // ---- copy-out ----
    float* __restrict__ dstRe = dst;
    float* __restrict__ dstIm = dst + NSTATE;
#pragma unroll
    for (int h = 0; h < 2; h++) {
#pragma unroll
        for (int cc = 0; cc < 16; cc++) {
            unsigned gHi = 0, sHi = 0;
#pragma unroll
            for (int jj = 0; jj < 4; jj++)
                if ((cc >> jj) & 1) {
                    gHi |= 1u << pArr[8 + jj];
                    sHi |= 1u << slotArr[8 + jj];
                }
            unsigned g = outer + gHi + gLoH[h];
            float2 v = S[SADDR2(sHi + sLoH[h])];
            dstRe[g] = v.x;
            dstIm[g] = v.y;
        }
    }
}

extern "C" void kernel_launch(void* const* d_in, const int* in_sizes, int n_in,
                              void* d_out, int out_size) {
    const float* state   = (const float*)d_in[0];
    const int*   targets = (const int*)d_in[1];
    const float* gates   = (const float*)d_in[2];
    float*       out     = (float*)d_out;

    dim3 block(128);
    dim3 grid(NBLOCKS);

    qstep3_kernel<<<grid, block>>>(state, out, gates, targets, 0, 1, 2);
    qstep3_kernel<<<grid, block>>>(out, out, gates, targets, 3, 4, 5);
    qstep3_kernel<<<grid, block>>>(out, out, gates, targets, 6, 7, -1);
}

// round 8
// speedup vs baseline: 1.5434x; 1.5434x over previous
#include <cuda_runtime.h>
#include <cstdint>

// QuantumCircuitSimulator2: 24 qubits, 8 steps of 4-qubit (16x16 complex) gates.
// Round-2 architecture (one gate per kernel, per-thread 16-amplitude group,
// global gather/scatter) improved:
//   - state held as interleaved float2 in a __device__ scratch between steps
//     (first kernel converts planar->interleaved, last converts back)
//   - 4-mult complex matvec on fma.rn.f32x2 (2 tables, 4 chains)
//   - 3 blocks/SM via reduced register footprint

#define NQ 24
#define NSTATE (1u << NQ)
#define NGROUPS (1u << (NQ - 4))
#define NSTEPS 8

typedef unsigned long long u64;

// interleaved scratch state (float2 per amplitude) — static device array
__device__ __align__(16) float QS_scratch[1u << 25];

__device__ __forceinline__ u64 fma2(u64 a, u64 b, u64 c) {
    u64 d;
    asm("fma.rn.f32x2 %0, %1, %2, %3;" : "=l"(d) : "l"(a), "l"(b), "l"(c));
    return d;
}
__device__ __forceinline__ u64 add2(u64 a, u64 b) {
    u64 d;
    asm("add.rn.f32x2 %0, %1, %2;" : "=l"(d) : "l"(a), "l"(b));
    return d;
}
__device__ __forceinline__ u64 pack2(float lo, float hi) {
    u64 d;
    asm("mov.b64 %0, {%1, %2};" : "=l"(d) : "f"(lo), "f"(hi));
    return d;
}
__device__ __forceinline__ void unpack2(u64 v, float& lo, float& hi) {
    asm("mov.b64 {%0, %1}, %2;" : "=f"(lo), "=f"(hi) : "l"(v));
}

// IN_PLANAR: src is [2, 2^24] planar re/im. Otherwise interleaved float2.
// OUT_PLANAR: dst is planar. Otherwise interleaved float2.
template <int IN_PLANAR, int OUT_PLANAR>
__global__ __launch_bounds__(256, 3)
void qgate_kernel(const float* __restrict__ src,
                  float* __restrict__ dst,
                  const float* __restrict__ gates,
                  const int* __restrict__ targets_raw,
                  int step) {
    __shared__ __align__(16) float sGr[256];
    __shared__ __align__(16) float sGi[256];

    const int tid = threadIdx.x;

    // raw gate tables (gr, gi) for this step
    {
        const float* g = gates + (size_t)step * 512;
        sGr[tid] = g[tid];
        sGi[tid] = g[256 + tid];
    }

    // dtype detect: int64 targets (<24) have zero odd 32-bit words
    int stride = (targets_raw[1] == 0 && targets_raw[3] == 0) ? 2 : 1;
    int q0 = targets_raw[(step * 4 + 0) * stride];
    int q1 = targets_raw[(step * 4 + 1) * stride];
    int q2 = targets_raw[(step * 4 + 2) * stride];
    int q3 = targets_raw[(step * 4 + 3) * stride];
    unsigned m0 = 1u << q0, m1 = 1u << q1, m2 = 1u << q2, m3 = 1u << q3;

    // sorted copy for ascending zero-bit insertion
    int a = q0, b = q1, c = q2, d = q3, t;
    if (a > b) { t = a; a = b; b = t; }
    if (c > d) { t = c; c = d; d = t; }
    if (a > c) { t = a; a = c; c = t; }
    if (b > d) { t = b; b = d; d = t; }
    if (b > c) { t = b; b = c; c = t; }

    unsigned g20 = blockIdx.x * 256u + tid;
    unsigned base = g20;
    base = ((base >> a) << (a + 1)) | (base & ((1u << a) - 1u));
    base = ((base >> b) << (b + 1)) | (base & ((1u << b) - 1u));
    base = ((base >> c) << (c + 1)) | (base & ((1u << c) - 1u));
    base = ((base >> d) << (d + 1)) | (base & ((1u << d) - 1u));

    // ---- gather 16 amplitudes, pack along k into f32x2 pairs ----
    u64 sr2[8], si2[8];
#pragma unroll
    for (int kk = 0; kk < 8; kk++) {
        unsigned o0 = base + (((2 * kk) & 1) ? m0 : 0u) + ((kk & 1) ? m1 : 0u) +
                      ((kk & 2) ? m2 : 0u) + ((kk & 4) ? m3 : 0u);
        unsigned o1 = o0 + m0;
        float r0, i0, r1, i1;
        if (IN_PLANAR) {
            r0 = src[o0];
            i0 = src[NSTATE + o0];
            r1 = src[o1];
            i1 = src[NSTATE + o1];
        } else {
            const float2* s2 = reinterpret_cast<const float2*>(src);
            float2 v0 = s2[o0];
            float2 v1 = s2[o1];
            r0 = v0.x; i0 = v0.y;
            r1 = v1.x; i1 = v1.y;
        }
        sr2[kk] = pack2(r0, r1);
        si2[kk] = pack2(i0, i1);
    }

    __syncthreads();  // tables ready (gathers overlap the table fill)

    const u64 NEG1 = pack2(-1.0f, -1.0f);
#pragma unroll
    for (int j = 0; j < 16; j++) {
        const float4* Gr4 = reinterpret_cast<const float4*>(sGr + j * 16);
        const float4* Gi4 = reinterpret_cast<const float4*>(sGi + j * 16);
        u64 a1 = 0ull, a2 = 0ull, a3 = 0ull, a4 = 0ull;
#pragma unroll
        for (int q = 0; q < 4; q++) {
            float4 gr = Gr4[q];
            float4 gi = Gi4[q];
            u64 grLo = pack2(gr.x, gr.y), grHi = pack2(gr.z, gr.w);
            u64 giLo = pack2(gi.x, gi.y), giHi = pack2(gi.z, gi.w);
            a1 = fma2(grLo, sr2[2 * q], a1);      // gr*sr
            a2 = fma2(giLo, si2[2 * q], a2);      // gi*si
            a3 = fma2(grLo, si2[2 * q], a3);      // gr*si
            a4 = fma2(giLo, sr2[2 * q], a4);      // gi*sr
            a1 = fma2(grHi, sr2[2 * q + 1], a1);
            a2 = fma2(giHi, si2[2 * q + 1], a2);
            a3 = fma2(grHi, si2[2 * q + 1], a3);
            a4 = fma2(giHi, sr2[2 * q + 1], a4);
        }
        u64 dre = fma2(a2, NEG1, a1);   // a1 - a2
        u64 dim = add2(a3, a4);         // a3 + a4
        float rl, rh, il, ih;
        unpack2(dre, rl, rh);
        unpack2(dim, il, ih);
        float re = rl + rh;
        float im = il + ih;
        unsigned oj = base + ((j & 1) ? m0 : 0u) + ((j & 2) ? m1 : 0u) +
                      ((j & 4) ? m2 : 0u) + ((j & 8) ? m3 : 0u);
        if (OUT_PLANAR) {
            dst[oj] = re;
            dst[NSTATE + oj] = im;
        } else {
            reinterpret_cast<float2*>(dst)[oj] = make_float2(re, im);
        }
    }
}

extern "C" void kernel_launch(void* const* d_in, const int* in_sizes, int n_in,
                              void* d_out, int out_size) {
    const float* state   = (const float*)d_in[0];
    const int*   targets = (const int*)d_in[1];
    const float* gates   = (const float*)d_in[2];
    float*       out     = (float*)d_out;

    void* scratch_ptr = nullptr;
    cudaGetSymbolAddress(&scratch_ptr, QS_scratch);
    float* scratch = (float*)scratch_ptr;

    dim3 block(256);
    dim3 grid(NGROUPS / 256);  // 4096 blocks

    // step 0: planar input -> interleaved scratch
    qgate_kernel<1, 0><<<grid, block>>>(state, scratch, gates, targets, 0);
    // steps 1..6: interleaved in-place (each thread owns its group)
    for (int s = 1; s < NSTEPS - 1; s++) {
        qgate_kernel<0, 0><<<grid, block>>>(scratch, scratch, gates, targets, s);
    }
    // step 7: interleaved -> planar output
    qgate_kernel<0, 1><<<grid, block>>>(scratch, out, gates, targets, NSTEPS - 1);
}